// round 7
// baseline (speedup 1.0000x reference)
#include <cuda_runtime.h>
#include <cstdint>
#include <math.h>

#define NTOK   4096
#define DMODEL 1024
#define DHID   256
#define NHEADS 4
#define HDIM   256

// ---------------- scratch (__device__ globals; no allocation allowed) -------
__device__ float    g_h  [NTOK * DHID];
__device__ int      g_mask[NTOK];
__device__ float    g_S  [(size_t)NHEADS * NTOK * NTOK];      // 268MB
// bf16 hi/lo planes (u32 = 2 bf16 along K)
__device__ uint32_t g_qh [NTOK * 512],  g_ql [NTOK * 512];    // input q
__device__ uint32_t g_kh [NTOK * 512],  g_kl [NTOK * 512];    // input k
__device__ uint32_t g_vh [NTOK * 512],  g_vl [NTOK * 512];    // input v
__device__ uint32_t g_w1h[DHID * 512],  g_w1l[DHID * 512];
__device__ uint32_t g_wqh[DMODEL * 512], g_wql[DMODEL * 512];
__device__ uint32_t g_wkh[DMODEL * 512], g_wkl[DMODEL * 512];
__device__ uint32_t g_wvh[DMODEL * 512], g_wvl[DMODEL * 512];
__device__ uint32_t g_woh[DMODEL * 512], g_wol[DMODEL * 512];
__device__ uint32_t g_qph[NTOK * 512],  g_qpl[NTOK * 512];    // Q proj
__device__ uint32_t g_kph[NTOK * 512],  g_kpl[NTOK * 512];    // K proj
__device__ uint32_t g_vph[NTOK * 512],  g_vpl[NTOK * 512];    // V proj
__device__ uint32_t g_vth[DMODEL * 2048], g_vtl[DMODEL * 2048]; // V^T
__device__ uint32_t g_ph [(size_t)NHEADS * NTOK * 2048];      // P hi
__device__ uint32_t g_pl [(size_t)NHEADS * NTOK * 2048];      // P lo
__device__ uint32_t g_cxh[NTOK * 512],  g_cxl[NTOK * 512];    // ctx

// ---------------- helpers ----------------------------------------------------
__device__ __forceinline__ uint32_t pack2(float x0, float x1) {
    uint32_t r;
    asm("cvt.rn.bf16x2.f32 %0, %1, %2;" : "=r"(r) : "f"(x1), "f"(x0));
    return r;
}
__device__ __forceinline__ void split2(float x0, float x1,
                                       uint32_t& h, uint32_t& l) {
    uint32_t hb = pack2(x0, x1);
    float f0 = __uint_as_float(hb << 16);
    float f1 = __uint_as_float(hb & 0xffff0000u);
    l = pack2(x0 - f0, x1 - f1);
    h = hb;
}
__device__ __forceinline__ void mma16816(float* c, const uint32_t* a,
                                         const uint32_t* b) {
    asm volatile(
        "mma.sync.aligned.m16n8k16.row.col.f32.bf16.bf16.f32 "
        "{%0,%1,%2,%3}, {%4,%5,%6,%7}, {%8,%9}, {%0,%1,%2,%3};"
        : "+f"(c[0]), "+f"(c[1]), "+f"(c[2]), "+f"(c[3])
        : "r"(a[0]), "r"(a[1]), "r"(a[2]), "r"(a[3]), "r"(b[0]), "r"(b[1]));
}
__device__ __forceinline__ uint32_t smem_u32(const void* p) {
    uint32_t a;
    asm("{ .reg .u64 t; cvta.to.shared.u64 t, %1; cvt.u32.u64 %0, t; }"
        : "=r"(a) : "l"(p));
    return a;
}
__device__ __forceinline__ void ldsm4(uint32_t& r0, uint32_t& r1,
                                      uint32_t& r2, uint32_t& r3,
                                      uint32_t addr) {
    asm volatile("ldmatrix.sync.aligned.m8n8.x4.shared.b16 {%0,%1,%2,%3}, [%4];"
                 : "=r"(r0), "=r"(r1), "=r"(r2), "=r"(r3) : "r"(addr));
}
__device__ __forceinline__ void cp16(uint32_t dst, const void* src) {
    asm volatile("cp.async.cg.shared.global [%0], [%1], 16;"
                 :: "r"(dst), "l"(src));
}
#define CP_COMMIT() asm volatile("cp.async.commit_group;" ::: "memory")
#define CP_WAIT0()  asm volatile("cp.async.wait_group 0;" ::: "memory")

// ---------------- unified 3xBF16 GEMM on pre-split planes --------------------
// D[M,N] = A[M,K] @ B[N,K]^T. A/B given as bf16 hi/lo u32 planes (2 elem/u32).
// CTA 128x128, K-chunk 32 elem (16 u32), 8 warps (4x2). lda/ldb in u32.
enum { EPI_RAW = 0, EPI_BIAS, EPI_RELU, EPI_QSCALE, EPI_KEYMASK, EPI_ROWMASK };

#define SROW   20                      // u32 per smem row (16 data + 4 pad)
#define STG_U  (128 * SROW)
#define STG_B  (4 * STG_U * 4)         // Ah|Al|Bh|Bl = 40960 bytes
#define SMEM_BYTES (2 * STG_B)

__device__ __forceinline__ void cp_chunk(
    const uint32_t* __restrict__ Ah, const uint32_t* __restrict__ Al, int lda,
    const uint32_t* __restrict__ Bh, const uint32_t* __restrict__ Bl, int ldb,
    int k0u, uint32_t sdst, int tid)
{
#pragma unroll
    for (int i = 0; i < 8; i++) {
        const int arr = i >> 1;               // 0:Ah 1:Al 2:Bh 3:Bl
        int j = ((i & 1) << 8) + tid;         // 0..511
        int r = j >> 2, c4 = (j & 3) * 4;
        const uint32_t* base = (arr == 0) ? Ah : (arr == 1) ? Al
                             : (arr == 2) ? Bh : Bl;
        const int ld = (arr < 2) ? lda : ldb;
        cp16(sdst + (uint32_t)(arr * STG_U + r * SROW + c4) * 4,
             base + (long)r * ld + k0u + c4);
    }
}

template <int EPI, int WBF>
__global__ __launch_bounds__(256, 1) void gemm_bf(
    const uint32_t* __restrict__ Ah, const uint32_t* __restrict__ Al,
    int lda, long aZ,
    const uint32_t* __restrict__ Bh, const uint32_t* __restrict__ Bl,
    int ldb, long bZ,
    float* __restrict__ C, uint32_t* __restrict__ Ch,
    uint32_t* __restrict__ Cl, int ldc, long cZ,
    int K, const float* __restrict__ bias,
    const int* __restrict__ mask, float scale)
{
    extern __shared__ __align__(16) char smem[];
    const int tid = threadIdx.x;
    const int wid = tid >> 5, lane = tid & 31;
    const int wm = wid & 3, wn = wid >> 2;
    const int qr = lane >> 2, qc = lane & 3;
    const int bm = blockIdx.y * 128, bn = blockIdx.x * 128;

    Ah += blockIdx.z * aZ + (long)bm * lda;
    Al += blockIdx.z * aZ + (long)bm * lda;
    Bh += blockIdx.z * bZ + (long)bn * ldb;
    Bl += blockIdx.z * bZ + (long)bn * ldb;
    if (WBF) { Ch += blockIdx.z * cZ; Cl += blockIdx.z * cZ; }
    else     { C  += blockIdx.z * cZ; }

    // ldmatrix per-lane offsets (u32 units within one plane sub-array)
    const int a_off = (wm * 32 + ((lane >> 3) & 1) * 8 + (lane & 7)) * SROW +
                      (lane >> 4) * 4;
    const int b_off = (wn * 64 + (lane >> 4) * 8 + (lane & 7)) * SROW +
                      ((lane >> 3) & 1) * 4;

    float acc[2][8][4];
#pragma unroll
    for (int mf = 0; mf < 2; mf++)
#pragma unroll
        for (int nf = 0; nf < 8; nf++)
#pragma unroll
            for (int j = 0; j < 4; j++) acc[mf][nf][j] = 0.f;

    const int nc = K / 32;
    cp_chunk(Ah, Al, lda, Bh, Bl, ldb, 0, smem_u32(smem), tid);
    CP_COMMIT();

    for (int c = 0; c < nc; c++) {
        CP_WAIT0();
        __syncthreads();
        if (c + 1 < nc) {
            cp_chunk(Ah, Al, lda, Bh, Bl, ldb, (c + 1) * 16,
                     smem_u32(smem + ((c + 1) & 1) * STG_B), tid);
            CP_COMMIT();
        }
        const uint32_t sb = smem_u32(smem + (c & 1) * STG_B);
#pragma unroll
        for (int kk = 0; kk < 2; kk++) {
            uint32_t ah[2][4], al[2][4], bh[8][2], bl[8][2];
#pragma unroll
            for (int mf = 0; mf < 2; mf++) {
                uint32_t ao = sb + (uint32_t)(a_off + mf * 16 * SROW + kk * 8) * 4;
                ldsm4(ah[mf][0], ah[mf][1], ah[mf][2], ah[mf][3], ao);
                ldsm4(al[mf][0], al[mf][1], al[mf][2], al[mf][3],
                      ao + STG_U * 4);
            }
#pragma unroll
            for (int p = 0; p < 4; p++) {
                uint32_t bo = sb + 2 * STG_U * 4 +
                              (uint32_t)(b_off + p * 16 * SROW + kk * 8) * 4;
                ldsm4(bh[2 * p][0], bh[2 * p][1],
                      bh[2 * p + 1][0], bh[2 * p + 1][1], bo);
                ldsm4(bl[2 * p][0], bl[2 * p][1],
                      bl[2 * p + 1][0], bl[2 * p + 1][1], bo + STG_U * 4);
            }
#pragma unroll
            for (int mf = 0; mf < 2; mf++)
#pragma unroll
                for (int nf = 0; nf < 8; nf++) {
                    mma16816(acc[mf][nf], ah[mf], bh[nf]);
                    mma16816(acc[mf][nf], ah[mf], bl[nf]);
                    mma16816(acc[mf][nf], al[mf], bh[nf]);
                }
        }
    }

#pragma unroll
    for (int mf = 0; mf < 2; mf++) {
        const int r0 = bm + wm * 32 + mf * 16 + qr;
        const int r1 = r0 + 8;
        int keep0 = 1, keep1 = 1;
        if (EPI == EPI_ROWMASK) { keep0 = mask[r0]; keep1 = mask[r1]; }
#pragma unroll
        for (int nf = 0; nf < 8; nf++) {
            const int cc = bn + wn * 64 + nf * 8 + qc * 2;
            float v0 = acc[mf][nf][0], v1 = acc[mf][nf][1];
            float v2 = acc[mf][nf][2], v3 = acc[mf][nf][3];
            if (EPI == EPI_BIAS || EPI == EPI_RELU || EPI == EPI_QSCALE ||
                EPI == EPI_ROWMASK) {
                float b0 = bias[cc], b1 = bias[cc + 1];
                v0 += b0; v1 += b1; v2 += b0; v3 += b1;
            }
            if (EPI == EPI_RELU) {
                v0 = fmaxf(v0, 0.f); v1 = fmaxf(v1, 0.f);
                v2 = fmaxf(v2, 0.f); v3 = fmaxf(v3, 0.f);
            }
            if (EPI == EPI_QSCALE) {
                v0 *= scale; v1 *= scale; v2 *= scale; v3 *= scale;
            }
            if (EPI == EPI_KEYMASK) {
                if (!mask[cc])     { v0 = -1e9f; v2 = -1e9f; }
                if (!mask[cc + 1]) { v1 = -1e9f; v3 = -1e9f; }
            }
            if (EPI == EPI_ROWMASK) {
                if (!keep0) { v0 = 0.f; v1 = 0.f; }
                if (!keep1) { v2 = 0.f; v3 = 0.f; }
            }
            if (WBF) {
                uint32_t h01, l01;
                split2(v0, v1, h01, l01);
                Ch[(long)r0 * (ldc >> 1) + (cc >> 1)] = h01;
                Cl[(long)r0 * (ldc >> 1) + (cc >> 1)] = l01;
                split2(v2, v3, h01, l01);
                Ch[(long)r1 * (ldc >> 1) + (cc >> 1)] = h01;
                Cl[(long)r1 * (ldc >> 1) + (cc >> 1)] = l01;
            } else {
                float2 o0 = {v0, v1}, o1 = {v2, v3};
                *(float2*)&C[(long)r0 * ldc + cc] = o0;
                *(float2*)&C[(long)r1 * ldc + cc] = o1;
            }
        }
    }
}

// ---------------- split fp32 -> bf16 hi/lo planes ----------------------------
__global__ void split_k(const float4* __restrict__ in,
                        uint32_t* __restrict__ ph, uint32_t* __restrict__ pl)
{
    long i = (long)blockIdx.x * 256 + threadIdx.x;   // over NTOK*DMODEL/4
    float4 v = in[i];
    uint32_t h0, l0, h1, l1;
    split2(v.x, v.y, h0, l0);
    split2(v.z, v.w, h1, l1);
    uint2 h = {h0, h1}, l = {l0, l1};
    ((uint2*)ph)[i] = h;
    ((uint2*)pl)[i] = l;
}

// transpose + split: in [R][C] fp32 -> planes [C][R/2] u32
__global__ void transpose_split(const float* __restrict__ in,
                                uint32_t* __restrict__ oh,
                                uint32_t* __restrict__ ol, int R, int C)
{
    __shared__ float t[32][33];
    const int bx = blockIdx.x * 32, by = blockIdx.y * 32;
    const int tx = threadIdx.x, ty = threadIdx.y;
#pragma unroll
    for (int j = 0; j < 32; j += 8)
        t[ty + j][tx] = in[(long)(by + ty + j) * C + bx + tx];
    __syncthreads();
#pragma unroll
    for (int j = 0; j < 16; j += 8) {
        int p = ty + j;                     // row-pair 0..15
        uint32_t h, l;
        split2(t[2 * p][tx], t[2 * p + 1][tx], h, l);
        long o = (long)(bx + tx) * (R >> 1) + (by >> 1) + p;
        oh[o] = h;
        ol[o] = l;
    }
}

// transpose bf16 planes (u16 view): in [R][C] -> out [C][R]; z picks hi/lo
__global__ void transpose_bf(const uint16_t* __restrict__ inh,
                             const uint16_t* __restrict__ inl,
                             uint16_t* __restrict__ outh,
                             uint16_t* __restrict__ outl, int R, int C)
{
    __shared__ uint16_t t[32][34];
    const uint16_t* in = blockIdx.z ? inl : inh;
    uint16_t* out = blockIdx.z ? outl : outh;
    const int bx = blockIdx.x * 32, by = blockIdx.y * 32;
#pragma unroll
    for (int j = 0; j < 32; j += 8)
        t[threadIdx.y + j][threadIdx.x] =
            in[(long)(by + threadIdx.y + j) * C + bx + threadIdx.x];
    __syncthreads();
#pragma unroll
    for (int j = 0; j < 32; j += 8)
        out[(long)(bx + threadIdx.y + j) * R + by + threadIdx.x] =
            t[threadIdx.x][threadIdx.y + j];
}

// ---------------- mask: sigmoid(h @ w2 + b2) > 0.15 --------------------------
__global__ void score_k(const float* __restrict__ h, const float* __restrict__ w2,
                        const float* __restrict__ b2, int* __restrict__ mask)
{
    const int warp = (blockIdx.x * blockDim.x + threadIdx.x) >> 5;
    const int lane = threadIdx.x & 31;
    if (warp >= NTOK) return;
    const float* hr = h + warp * DHID;
    float s = 0.f;
#pragma unroll
    for (int i = 0; i < DHID / 32; i++)
        s += hr[lane + i * 32] * w2[lane + i * 32];
#pragma unroll
    for (int o = 16; o; o >>= 1) s += __shfl_xor_sync(0xffffffffu, s, o);
    if (lane == 0) {
        float sig = 1.0f / (1.0f + expf(-(s + b2[0])));
        mask[warp] = (sig > 0.15f) ? 1 : 0;
    }
}

// ---------------- row softmax: S fp32 -> P bf16 hi/lo planes -----------------
__global__ __launch_bounds__(256) void softmax_k(
    const float* __restrict__ S, uint32_t* __restrict__ ph,
    uint32_t* __restrict__ pl)
{
    __shared__ float cache[NTOK];
    __shared__ float red[256];
    const size_t row = (size_t)blockIdx.y * NTOK + blockIdx.x;
    const float* Sr = S + row * NTOK;
    const int tid = threadIdx.x;

    float m = -3.4e38f;
#pragma unroll
    for (int i = 0; i < 4; i++) {
        float4 v = *(const float4*)&Sr[(tid + i * 256) * 4];
        m = fmaxf(m, fmaxf(fmaxf(v.x, v.y), fmaxf(v.z, v.w)));
    }
    red[tid] = m;
    __syncthreads();
    for (int s = 128; s; s >>= 1) {
        if (tid < s) red[tid] = fmaxf(red[tid], red[tid + s]);
        __syncthreads();
    }
    m = red[0];
    __syncthreads();

    float sum = 0.f;
#pragma unroll
    for (int i = 0; i < 4; i++) {
        int f4 = tid + i * 256;
        float4 v = *(const float4*)&Sr[f4 * 4];
        float4 p;
        p.x = __expf(v.x - m); p.y = __expf(v.y - m);
        p.z = __expf(v.z - m); p.w = __expf(v.w - m);
        *(float4*)&cache[f4 * 4] = p;
        sum += p.x + p.y + p.z + p.w;
    }
    red[tid] = sum;
    __syncthreads();
    for (int s = 128; s; s >>= 1) {
        if (tid < s) red[tid] += red[tid + s];
        __syncthreads();
    }
    const float inv = 1.0f / red[0];
    uint2* Ph = (uint2*)(ph + row * 2048);
    uint2* Pl = (uint2*)(pl + row * 2048);
#pragma unroll
    for (int i = 0; i < 4; i++) {
        int f4 = tid + i * 256;
        float4 p = *(const float4*)&cache[f4 * 4];
        uint32_t h0, l0, h1, l1;
        split2(p.x * inv, p.y * inv, h0, l0);
        split2(p.z * inv, p.w * inv, h1, l1);
        uint2 h = {h0, h1}, l = {l0, l1};
        Ph[f4] = h;
        Pl[f4] = l;
    }
}

// ---------------------------------------------------------------------------
extern "C" void kernel_launch(void* const* d_in, const int* in_sizes, int n_in,
                              void* d_out, int out_size)
{
    const float* q  = (const float*)d_in[0];
    const float* k  = (const float*)d_in[1];
    const float* v  = (const float*)d_in[2];
    const float* w1 = (const float*)d_in[3];
    const float* b1 = (const float*)d_in[4];
    const float* w2 = (const float*)d_in[5];
    const float* b2 = (const float*)d_in[6];
    const float* wq = (const float*)d_in[7];
    const float* bq = (const float*)d_in[8];
    const float* wk = (const float*)d_in[9];
    const float* bk = (const float*)d_in[10];
    const float* wv = (const float*)d_in[11];
    const float* bv = (const float*)d_in[12];
    const float* wo = (const float*)d_in[13];
    const float* bo = (const float*)d_in[14];
    float* out = (float*)d_out;

    float *hh, *S;
    int* msk;
    uint32_t *qh, *ql, *kh, *kl, *vh, *vl;
    uint32_t *w1h, *w1l, *wqh, *wql, *wkh, *wkl, *wvh, *wvl, *woh, *wol;
    uint32_t *qph, *qpl, *kph, *kpl, *vph, *vpl, *vth, *vtl;
    uint32_t *ph, *pl, *cxh, *cxl;
    cudaGetSymbolAddress((void**)&hh,  g_h);
    cudaGetSymbolAddress((void**)&msk, g_mask);
    cudaGetSymbolAddress((void**)&S,   g_S);
    cudaGetSymbolAddress((void**)&qh,  g_qh);  cudaGetSymbolAddress((void**)&ql,  g_ql);
    cudaGetSymbolAddress((void**)&kh,  g_kh);  cudaGetSymbolAddress((void**)&kl,  g_kl);
    cudaGetSymbolAddress((void**)&vh,  g_vh);  cudaGetSymbolAddress((void**)&vl,  g_vl);
    cudaGetSymbolAddress((void**)&w1h, g_w1h); cudaGetSymbolAddress((void**)&w1l, g_w1l);
    cudaGetSymbolAddress((void**)&wqh, g_wqh); cudaGetSymbolAddress((void**)&wql, g_wql);
    cudaGetSymbolAddress((void**)&wkh, g_wkh); cudaGetSymbolAddress((void**)&wkl, g_wkl);
    cudaGetSymbolAddress((void**)&wvh, g_wvh); cudaGetSymbolAddress((void**)&wvl, g_wvl);
    cudaGetSymbolAddress((void**)&woh, g_woh); cudaGetSymbolAddress((void**)&wol, g_wol);
    cudaGetSymbolAddress((void**)&qph, g_qph); cudaGetSymbolAddress((void**)&qpl, g_qpl);
    cudaGetSymbolAddress((void**)&kph, g_kph); cudaGetSymbolAddress((void**)&kpl, g_kpl);
    cudaGetSymbolAddress((void**)&vph, g_vph); cudaGetSymbolAddress((void**)&vpl, g_vpl);
    cudaGetSymbolAddress((void**)&vth, g_vth); cudaGetSymbolAddress((void**)&vtl, g_vtl);
    cudaGetSymbolAddress((void**)&ph,  g_ph);  cudaGetSymbolAddress((void**)&pl,  g_pl);
    cudaGetSymbolAddress((void**)&cxh, g_cxh); cudaGetSymbolAddress((void**)&cxl, g_cxl);

    cudaFuncSetAttribute(gemm_bf<EPI_RELU, 0>,
        cudaFuncAttributeMaxDynamicSharedMemorySize, SMEM_BYTES);
    cudaFuncSetAttribute(gemm_bf<EPI_QSCALE, 1>,
        cudaFuncAttributeMaxDynamicSharedMemorySize, SMEM_BYTES);
    cudaFuncSetAttribute(gemm_bf<EPI_BIAS, 1>,
        cudaFuncAttributeMaxDynamicSharedMemorySize, SMEM_BYTES);
    cudaFuncSetAttribute(gemm_bf<EPI_KEYMASK, 0>,
        cudaFuncAttributeMaxDynamicSharedMemorySize, SMEM_BYTES);
    cudaFuncSetAttribute(gemm_bf<EPI_RAW, 1>,
        cudaFuncAttributeMaxDynamicSharedMemorySize, SMEM_BYTES);
    cudaFuncSetAttribute(gemm_bf<EPI_ROWMASK, 0>,
        cudaFuncAttributeMaxDynamicSharedMemorySize, SMEM_BYTES);

    dim3 tb(32, 8);
    // 0) pre-split inputs + weights into bf16 hi/lo planes
    split_k<<<NTOK * DMODEL / 1024, 256>>>((const float4*)q, qh, ql);
    split_k<<<NTOK * DMODEL / 1024, 256>>>((const float4*)k, kh, kl);
    split_k<<<NTOK * DMODEL / 1024, 256>>>((const float4*)v, vh, vl);
    transpose_split<<<dim3(DHID / 32, DMODEL / 32), tb>>>(w1, w1h, w1l,
                                                          DMODEL, DHID);
    transpose_split<<<dim3(32, 32), tb>>>(wq, wqh, wql, DMODEL, DMODEL);
    transpose_split<<<dim3(32, 32), tb>>>(wk, wkh, wkl, DMODEL, DMODEL);
    transpose_split<<<dim3(32, 32), tb>>>(wv, wvh, wvl, DMODEL, DMODEL);
    transpose_split<<<dim3(32, 32), tb>>>(wo, woh, wol, DMODEL, DMODEL);

    // 1) predictor hidden: h = relu(q @ w1 + b1)
    gemm_bf<EPI_RELU, 0><<<dim3(DHID / 128, NTOK / 128), 256, SMEM_BYTES>>>(
        qh, ql, 512, 0, w1h, w1l, 512, 0,
        hh, nullptr, nullptr, DHID, 0, DMODEL, b1, nullptr, 0.f);
    // 2) token mask
    score_k<<<NTOK / 8, 256>>>(hh, w2, b2, msk);
    // 3) projections -> planes (softmax scale folded into Q)
    gemm_bf<EPI_QSCALE, 1><<<dim3(8, 32), 256, SMEM_BYTES>>>(
        qh, ql, 512, 0, wqh, wql, 512, 0,
        nullptr, qph, qpl, DMODEL, 0, DMODEL, bq, nullptr, 0.0625f);
    gemm_bf<EPI_BIAS, 1><<<dim3(8, 32), 256, SMEM_BYTES>>>(
        kh, kl, 512, 0, wkh, wkl, 512, 0,
        nullptr, kph, kpl, DMODEL, 0, DMODEL, bk, nullptr, 0.f);
    gemm_bf<EPI_BIAS, 1><<<dim3(8, 32), 256, SMEM_BYTES>>>(
        vh, vl, 512, 0, wvh, wvl, 512, 0,
        nullptr, vph, vpl, DMODEL, 0, DMODEL, bv, nullptr, 0.f);
    // 4) transpose V planes -> [1024][4096]
    transpose_bf<<<dim3(DMODEL / 32, NTOK / 32, 2), tb>>>(
        (const uint16_t*)vph, (const uint16_t*)vpl,
        (uint16_t*)vth, (uint16_t*)vtl, NTOK, DMODEL);
    // 5) S[h] = Q @ K^T (scaled), masked keys -> -1e9
    gemm_bf<EPI_KEYMASK, 0><<<dim3(32, 32, NHEADS), 256, SMEM_BYTES>>>(
        qph, qpl, 512, 128, kph, kpl, 512, 128,
        S, nullptr, nullptr, NTOK, (long)NTOK * NTOK, HDIM,
        nullptr, msk, 0.f);
    // 6) softmax rows -> P planes
    softmax_k<<<dim3(NTOK, NHEADS), 256>>>(S, ph, pl);
    // 7) ctx[h] = P @ V -> ctx planes
    gemm_bf<EPI_RAW, 1><<<dim3(HDIM / 128, 32, NHEADS), 256, SMEM_BYTES>>>(
        ph, pl, 2048, (long)NTOK * 2048, vth, vtl, 2048, (long)HDIM * 2048,
        nullptr, cxh, cxl, DMODEL, 128, NTOK, nullptr, nullptr, 0.f);
    // 8) out = rowmask(ctx @ wo + bo)
    gemm_bf<EPI_ROWMASK, 0><<<dim3(8, 32), 256, SMEM_BYTES>>>(
        cxh, cxl, 512, 0, woh, wol, 512, 0,
        out, nullptr, nullptr, DMODEL, 0, DMODEL, bo, msk, 0.f);
}

// round 8
// speedup vs baseline: 1.4205x; 1.4205x over previous
#include <cuda_runtime.h>
#include <cuda_fp16.h>
#include <cstdint>
#include <math.h>

#define NTOK   4096
#define DMODEL 1024
#define DHID   256
#define NHEADS 4
#define HDIM   256

// ---------------- scratch (__device__ globals; no allocation allowed) -------
__device__ float g_h  [NTOK * DHID];
__device__ int   g_mask[NTOK];
__device__ float g_qp [NTOK * DMODEL];
__device__ float g_kp [NTOK * DMODEL];
__device__ float g_vp [NTOK * DMODEL];
__device__ float g_ctx[NTOK * DMODEL];
__device__ float g_w1t[DHID * DMODEL];
__device__ float g_wqt[DMODEL * DMODEL];
__device__ float g_wkt[DMODEL * DMODEL];
__device__ float g_wvt[DMODEL * DMODEL];
__device__ float g_wot[DMODEL * DMODEL];
__device__ float g_vpt[DMODEL * NTOK];
__device__ float g_S  [(size_t)NHEADS * NTOK * NTOK];   // 268MB

// ---------------- fp16 helpers ----------------------------------------------
// A operand: split into fp16 hi + lo (lo = x - float(hi), |lo| <~ 2^-12 |x|)
__device__ __forceinline__ void split2h(float x0, float x1,
                                        uint32_t& h, uint32_t& l) {
    __half2 hv = __floats2half2_rn(x0, x1);
    float f0 = __low2float(hv), f1 = __high2float(hv);
    __half2 lv = __floats2half2_rn(x0 - f0, x1 - f1);
    h = *(uint32_t*)&hv;
    l = *(uint32_t*)&lv;
}
// B operand: hi plane only
__device__ __forceinline__ uint32_t pack2h(float x0, float x1) {
    __half2 hv = __floats2half2_rn(x0, x1);
    return *(uint32_t*)&hv;
}
__device__ __forceinline__ void mma16816(float* c, const uint32_t* a,
                                         const uint32_t* b) {
    asm volatile(
        "mma.sync.aligned.m16n8k16.row.col.f32.f16.f16.f32 "
        "{%0,%1,%2,%3}, {%4,%5,%6,%7}, {%8,%9}, {%0,%1,%2,%3};"
        : "+f"(c[0]), "+f"(c[1]), "+f"(c[2]), "+f"(c[3])
        : "r"(a[0]), "r"(a[1]), "r"(a[2]), "r"(a[3]), "r"(b[0]), "r"(b[1]));
}
__device__ __forceinline__ uint32_t smem_u32(const void* p) {
    uint32_t a;
    asm("{ .reg .u64 t; cvta.to.shared.u64 t, %1; cvt.u32.u64 %0, t; }"
        : "=r"(a) : "l"(p));
    return a;
}
__device__ __forceinline__ void ldsm4(uint32_t& r0, uint32_t& r1,
                                      uint32_t& r2, uint32_t& r3,
                                      uint32_t addr) {
    asm volatile("ldmatrix.sync.aligned.m8n8.x4.shared.b16 {%0,%1,%2,%3}, [%4];"
                 : "=r"(r0), "=r"(r1), "=r"(r2), "=r"(r3) : "r"(addr));
}

// ---------------- unified 2xFP16 tensor-core GEMM ---------------------------
// D[M,N] = A[M,K] @ B[N,K]^T (+ epilogue). CTA 128x128, K-chunk 32, 8 warps.
// acc = Ah*Bh + Al*Bh  (fp16 split on A, hi-only B; err ~2^-12)
enum { EPI_RAW = 0, EPI_BIAS, EPI_RELU, EPI_QSCALE, EPI_KEYMASK, EPI_ROWMASK };

#define SROW   20                      // u32 per smem row (16 data + 4 pad)
#define STG_U  (128 * SROW)
#define STG_B  (3 * STG_U * 4)         // Ah|Al|Bh = 30720 bytes
#define SMEM_BYTES (2 * STG_B)         // 61440

__device__ __forceinline__ void ldg_chunk(const float* __restrict__ Arow,
                                          int lda,
                                          const float* __restrict__ Brow,
                                          int ldb, int k0, int tid,
                                          float4* av, float4* bv) {
#pragma unroll
    for (int i = 0; i < 4; i++) {
        int idx = tid + i * 256;
        int r = idx >> 3, c4 = idx & 7;
        av[i] = *(const float4*)(Arow + (long)r * lda + k0 + c4 * 4);
        bv[i] = *(const float4*)(Brow + (long)r * ldb + k0 + c4 * 4);
    }
}
__device__ __forceinline__ void sts_chunk(uint32_t* st, int tid,
                                          const float4* av, const float4* bv) {
    uint32_t* Ah = st;
    uint32_t* Al = st + STG_U;
    uint32_t* Bh = st + 2 * STG_U;
#pragma unroll
    for (int i = 0; i < 4; i++) {
        int idx = tid + i * 256;
        int r = idx >> 3, c4 = idx & 7;
        uint32_t h01, l01, h23, l23;
        split2h(av[i].x, av[i].y, h01, l01);
        split2h(av[i].z, av[i].w, h23, l23);
        int o = r * SROW + c4 * 2;
        Ah[o] = h01; Ah[o + 1] = h23;
        Al[o] = l01; Al[o + 1] = l23;
        Bh[o] = pack2h(bv[i].x, bv[i].y);
        Bh[o + 1] = pack2h(bv[i].z, bv[i].w);
    }
}

template <int EPI>
__global__ __launch_bounds__(256, 1) void gemm_bf(
    const float* __restrict__ A, int lda, long aZ,
    const float* __restrict__ B, int ldb, long bZ,
    float* __restrict__ C, int ldc, long cZ,
    int K, const float* __restrict__ bias,
    const int* __restrict__ mask, float scale)
{
    extern __shared__ __align__(16) char smem[];
    const int tid = threadIdx.x;
    const int wid = tid >> 5, lane = tid & 31;
    const int wm = wid & 3, wn = wid >> 2;      // 4x2 warp grid
    const int qr = lane >> 2, qc = lane & 3;
    const int bm = blockIdx.y * 128, bn = blockIdx.x * 128;

    A += blockIdx.z * aZ;
    B += blockIdx.z * bZ;
    C += blockIdx.z * cZ;
    const float* Arow = A + (long)bm * lda;
    const float* Brow = B + (long)bn * ldb;

    // ldmatrix per-lane offsets (u32 units within one plane sub-array)
    const int a_off = (wm * 32 + ((lane >> 3) & 1) * 8 + (lane & 7)) * SROW +
                      (lane >> 4) * 4;            // + mf*16*SROW
    const int b_off = (wn * 64 + (lane >> 4) * 8 + (lane & 7)) * SROW +
                      ((lane >> 3) & 1) * 4;      // + p*16*SROW

    float acc[2][8][4];
#pragma unroll
    for (int mf = 0; mf < 2; mf++)
#pragma unroll
        for (int nf = 0; nf < 8; nf++)
#pragma unroll
            for (int j = 0; j < 4; j++) acc[mf][nf][j] = 0.f;

    const int nc = K / 32;
    float4 av[4], bv[4];
    ldg_chunk(Arow, lda, Brow, ldb, 0, tid, av, bv);
    sts_chunk((uint32_t*)smem, tid, av, bv);
    __syncthreads();

    for (int c = 0; c < nc; c++) {
        if (c + 1 < nc)
            ldg_chunk(Arow, lda, Brow, ldb, (c + 1) * 32, tid, av, bv);
        const uint32_t sb = smem_u32(smem + (c & 1) * STG_B);
#pragma unroll
        for (int kk = 0; kk < 2; kk++) {
            uint32_t ah[2][4], al[2][4], bh[8][2];
#pragma unroll
            for (int mf = 0; mf < 2; mf++) {
                uint32_t ao = sb + (uint32_t)(a_off + mf * 16 * SROW + kk * 8) * 4;
                ldsm4(ah[mf][0], ah[mf][1], ah[mf][2], ah[mf][3], ao);
                ldsm4(al[mf][0], al[mf][1], al[mf][2], al[mf][3],
                      ao + STG_U * 4);
            }
#pragma unroll
            for (int p = 0; p < 4; p++) {
                uint32_t bo = sb + 2 * STG_U * 4 +
                              (uint32_t)(b_off + p * 16 * SROW + kk * 8) * 4;
                ldsm4(bh[2 * p][0], bh[2 * p][1],
                      bh[2 * p + 1][0], bh[2 * p + 1][1], bo);
            }
#pragma unroll
            for (int mf = 0; mf < 2; mf++)
#pragma unroll
                for (int nf = 0; nf < 8; nf++) {
                    mma16816(acc[mf][nf], ah[mf], bh[nf]);
                    mma16816(acc[mf][nf], al[mf], bh[nf]);
                }
        }
        __syncthreads();
        if (c + 1 < nc) {
            sts_chunk((uint32_t*)(smem + ((c + 1) & 1) * STG_B), tid, av, bv);
            __syncthreads();
        }
    }

#pragma unroll
    for (int mf = 0; mf < 2; mf++) {
        const int r0 = bm + wm * 32 + mf * 16 + qr;
        const int r1 = r0 + 8;
        int keep0 = 1, keep1 = 1;
        if (EPI == EPI_ROWMASK) { keep0 = mask[r0]; keep1 = mask[r1]; }
#pragma unroll
        for (int nf = 0; nf < 8; nf++) {
            const int cc = bn + wn * 64 + nf * 8 + qc * 2;
            float v0 = acc[mf][nf][0], v1 = acc[mf][nf][1];
            float v2 = acc[mf][nf][2], v3 = acc[mf][nf][3];
            if (EPI == EPI_BIAS || EPI == EPI_RELU || EPI == EPI_QSCALE ||
                EPI == EPI_ROWMASK) {
                float b0 = bias[cc], b1 = bias[cc + 1];
                v0 += b0; v1 += b1; v2 += b0; v3 += b1;
            }
            if (EPI == EPI_RELU) {
                v0 = fmaxf(v0, 0.f); v1 = fmaxf(v1, 0.f);
                v2 = fmaxf(v2, 0.f); v3 = fmaxf(v3, 0.f);
            }
            if (EPI == EPI_QSCALE) {
                v0 *= scale; v1 *= scale; v2 *= scale; v3 *= scale;
            }
            if (EPI == EPI_KEYMASK) {
                if (!mask[cc])     { v0 = -1e9f; v2 = -1e9f; }
                if (!mask[cc + 1]) { v1 = -1e9f; v3 = -1e9f; }
            }
            if (EPI == EPI_ROWMASK) {
                if (!keep0) { v0 = 0.f; v1 = 0.f; }
                if (!keep1) { v2 = 0.f; v3 = 0.f; }
            }
            float2 o0 = {v0, v1}, o1 = {v2, v3};
            *(float2*)&C[(long)r0 * ldc + cc] = o0;
            *(float2*)&C[(long)r1 * ldc + cc] = o1;
        }
    }
}

// ---------------- transpose: out[C][R] = in[R][C]^T --------------------------
__global__ void transpose_k(const float* __restrict__ in, float* __restrict__ out,
                            int R, int C)
{
    __shared__ float t[32][33];
    const int bx = blockIdx.x * 32, by = blockIdx.y * 32;
#pragma unroll
    for (int j = 0; j < 32; j += 8)
        t[threadIdx.y + j][threadIdx.x] =
            in[(long)(by + threadIdx.y + j) * C + bx + threadIdx.x];
    __syncthreads();
#pragma unroll
    for (int j = 0; j < 32; j += 8)
        out[(long)(bx + threadIdx.y + j) * R + by + threadIdx.x] =
            t[threadIdx.x][threadIdx.y + j];
}

// ---------------- mask: sigmoid(h @ w2 + b2) > 0.15 --------------------------
__global__ void score_k(const float* __restrict__ h, const float* __restrict__ w2,
                        const float* __restrict__ b2, int* __restrict__ mask)
{
    const int warp = (blockIdx.x * blockDim.x + threadIdx.x) >> 5;
    const int lane = threadIdx.x & 31;
    if (warp >= NTOK) return;
    const float* hr = h + warp * DHID;
    float s = 0.f;
#pragma unroll
    for (int i = 0; i < DHID / 32; i++)
        s += hr[lane + i * 32] * w2[lane + i * 32];
#pragma unroll
    for (int o = 16; o; o >>= 1) s += __shfl_xor_sync(0xffffffffu, s, o);
    if (lane == 0) {
        float sig = 1.0f / (1.0f + expf(-(s + b2[0])));
        mask[warp] = (sig > 0.15f) ? 1 : 0;
    }
}

// ---------------- row softmax over 4096 keys (in place) ----------------------
__global__ __launch_bounds__(256) void softmax_k(float* __restrict__ S)
{
    __shared__ float cache[NTOK];
    __shared__ float red[256];
    float* Sr = S + ((size_t)blockIdx.y * NTOK + blockIdx.x) * NTOK;
    const int tid = threadIdx.x;

    float m = -3.4e38f;
#pragma unroll
    for (int i = 0; i < 4; i++) {
        float4 v = *(const float4*)&Sr[(tid + i * 256) * 4];
        m = fmaxf(m, fmaxf(fmaxf(v.x, v.y), fmaxf(v.z, v.w)));
    }
    red[tid] = m;
    __syncthreads();
    for (int s = 128; s; s >>= 1) {
        if (tid < s) red[tid] = fmaxf(red[tid], red[tid + s]);
        __syncthreads();
    }
    m = red[0];
    __syncthreads();

    float sum = 0.f;
#pragma unroll
    for (int i = 0; i < 4; i++) {
        int f4 = tid + i * 256;
        float4 v = *(const float4*)&Sr[f4 * 4];
        float4 p;
        p.x = __expf(v.x - m); p.y = __expf(v.y - m);
        p.z = __expf(v.z - m); p.w = __expf(v.w - m);
        *(float4*)&cache[f4 * 4] = p;
        sum += p.x + p.y + p.z + p.w;
    }
    red[tid] = sum;
    __syncthreads();
    for (int s = 128; s; s >>= 1) {
        if (tid < s) red[tid] += red[tid + s];
        __syncthreads();
    }
    const float inv = 1.0f / red[0];
#pragma unroll
    for (int i = 0; i < 4; i++) {
        int f4 = tid + i * 256;
        float4 p = *(float4*)&cache[f4 * 4];
        p.x *= inv; p.y *= inv; p.z *= inv; p.w *= inv;
        *(float4*)&Sr[f4 * 4] = p;
    }
}

// ---------------------------------------------------------------------------
extern "C" void kernel_launch(void* const* d_in, const int* in_sizes, int n_in,
                              void* d_out, int out_size)
{
    const float* q  = (const float*)d_in[0];
    const float* k  = (const float*)d_in[1];
    const float* v  = (const float*)d_in[2];
    const float* w1 = (const float*)d_in[3];
    const float* b1 = (const float*)d_in[4];
    const float* w2 = (const float*)d_in[5];
    const float* b2 = (const float*)d_in[6];
    const float* wq = (const float*)d_in[7];
    const float* bq = (const float*)d_in[8];
    const float* wk = (const float*)d_in[9];
    const float* bk = (const float*)d_in[10];
    const float* wv = (const float*)d_in[11];
    const float* bv = (const float*)d_in[12];
    const float* wo = (const float*)d_in[13];
    const float* bo = (const float*)d_in[14];
    float* out = (float*)d_out;

    float *hh, *qp, *kp, *vp, *ctx, *w1t, *wqt, *wkt, *wvt, *wot, *vpt, *S;
    int* msk;
    cudaGetSymbolAddress((void**)&hh,  g_h);
    cudaGetSymbolAddress((void**)&msk, g_mask);
    cudaGetSymbolAddress((void**)&qp,  g_qp);
    cudaGetSymbolAddress((void**)&kp,  g_kp);
    cudaGetSymbolAddress((void**)&vp,  g_vp);
    cudaGetSymbolAddress((void**)&ctx, g_ctx);
    cudaGetSymbolAddress((void**)&w1t, g_w1t);
    cudaGetSymbolAddress((void**)&wqt, g_wqt);
    cudaGetSymbolAddress((void**)&wkt, g_wkt);
    cudaGetSymbolAddress((void**)&wvt, g_wvt);
    cudaGetSymbolAddress((void**)&wot, g_wot);
    cudaGetSymbolAddress((void**)&vpt, g_vpt);
    cudaGetSymbolAddress((void**)&S,   g_S);

    cudaFuncSetAttribute(gemm_bf<EPI_RAW>,
        cudaFuncAttributeMaxDynamicSharedMemorySize, SMEM_BYTES);
    cudaFuncSetAttribute(gemm_bf<EPI_BIAS>,
        cudaFuncAttributeMaxDynamicSharedMemorySize, SMEM_BYTES);
    cudaFuncSetAttribute(gemm_bf<EPI_RELU>,
        cudaFuncAttributeMaxDynamicSharedMemorySize, SMEM_BYTES);
    cudaFuncSetAttribute(gemm_bf<EPI_QSCALE>,
        cudaFuncAttributeMaxDynamicSharedMemorySize, SMEM_BYTES);
    cudaFuncSetAttribute(gemm_bf<EPI_KEYMASK>,
        cudaFuncAttributeMaxDynamicSharedMemorySize, SMEM_BYTES);
    cudaFuncSetAttribute(gemm_bf<EPI_ROWMASK>,
        cudaFuncAttributeMaxDynamicSharedMemorySize, SMEM_BYTES);

    dim3 tb(32, 8);
    transpose_k<<<dim3(DHID / 32, DMODEL / 32), tb>>>(w1, w1t, DMODEL, DHID);
    transpose_k<<<dim3(32, 32), tb>>>(wq, wqt, DMODEL, DMODEL);
    transpose_k<<<dim3(32, 32), tb>>>(wk, wkt, DMODEL, DMODEL);
    transpose_k<<<dim3(32, 32), tb>>>(wv, wvt, DMODEL, DMODEL);
    transpose_k<<<dim3(32, 32), tb>>>(wo, wot, DMODEL, DMODEL);

    // 1) predictor hidden: h = relu(q @ w1 + b1)
    gemm_bf<EPI_RELU><<<dim3(DHID / 128, NTOK / 128), 256, SMEM_BYTES>>>(
        q, DMODEL, 0, w1t, DMODEL, 0, hh, DHID, 0, DMODEL, b1, nullptr, 0.f);
    // 2) token mask
    score_k<<<NTOK / 8, 256>>>(hh, w2, b2, msk);
    // 3) projections (softmax scale folded into qp)
    gemm_bf<EPI_QSCALE><<<dim3(8, 32), 256, SMEM_BYTES>>>(
        q, DMODEL, 0, wqt, DMODEL, 0, qp, DMODEL, 0, DMODEL, bq, nullptr,
        0.0625f);
    gemm_bf<EPI_BIAS><<<dim3(8, 32), 256, SMEM_BYTES>>>(
        k, DMODEL, 0, wkt, DMODEL, 0, kp, DMODEL, 0, DMODEL, bk, nullptr, 0.f);
    gemm_bf<EPI_BIAS><<<dim3(8, 32), 256, SMEM_BYTES>>>(
        v, DMODEL, 0, wvt, DMODEL, 0, vp, DMODEL, 0, DMODEL, bv, nullptr, 0.f);
    // 4) transpose V projection -> [1024][4096]
    transpose_k<<<dim3(DMODEL / 32, NTOK / 32), tb>>>(vp, vpt, NTOK, DMODEL);
    // 5) S[h] = qp @ kp^T, masked keys -> -1e9
    gemm_bf<EPI_KEYMASK><<<dim3(32, 32, NHEADS), 256, SMEM_BYTES>>>(
        qp, DMODEL, HDIM, kp, DMODEL, HDIM, S, NTOK, (long)NTOK * NTOK,
        HDIM, nullptr, msk, 0.f);
    // 6) softmax rows
    softmax_k<<<dim3(NTOK, NHEADS), 256>>>(S);
    // 7) ctx[h] = P @ V
    gemm_bf<EPI_RAW><<<dim3(HDIM / 128, 32, NHEADS), 256, SMEM_BYTES>>>(
        S, NTOK, (long)NTOK * NTOK, vpt, NTOK, (long)HDIM * NTOK,
        ctx, DMODEL, HDIM, NTOK, nullptr, nullptr, 0.f);
    // 8) out = rowmask(ctx @ wo + bo)
    gemm_bf<EPI_ROWMASK><<<dim3(8, 32), 256, SMEM_BYTES>>>(
        ctx, DMODEL, 0, wot, DMODEL, 0, out, DMODEL, 0, DMODEL, bo, msk, 0.f);
}